// round 1
// baseline (speedup 1.0000x reference)
#include <cuda_runtime.h>
#include <cuda_bf16.h>
#include <math.h>

#define NN 50000
#define EE 800000
#define HID 128
#define NH 4
#define HD 32

// ---------------- scratch (no allocation allowed) ----------------
// 8 slabs of N*HID floats: h0..h5, fs, fd
__device__ float g_buf[(size_t)8 * NN * HID];
// ints: deg[NN], row_ptr[NN+1], cur[NN], csr_src[EE]
__device__ int g_ibuf[NN + (NN + 1) + NN + EE];

__device__ __forceinline__ float gelu_tanh(float x) {
    float x3 = x * x * x;
    float t = tanhf(0.7978845608028654f * (x + 0.044715f * x3));
    return 0.5f * x * (1.0f + t);
}

// ---------------- CSR build ----------------
__global__ void hist_kernel(const int* __restrict__ dst, int* __restrict__ deg, int E) {
    int e = blockIdx.x * blockDim.x + threadIdx.x;
    if (e < E) atomicAdd(&deg[dst[e]], 1);
}

__global__ void scan_kernel(const int* __restrict__ deg, int* __restrict__ row_ptr, int n) {
    __shared__ int temp[1024];
    __shared__ int carry;
    if (threadIdx.x == 0) { carry = 0; row_ptr[0] = 0; }
    __syncthreads();
    for (int base = 0; base < n; base += 1024) {
        int i = base + threadIdx.x;
        int v = (i < n) ? deg[i] : 0;
        temp[threadIdx.x] = v;
        __syncthreads();
        for (int off = 1; off < 1024; off <<= 1) {
            int t = (threadIdx.x >= off) ? temp[threadIdx.x - off] : 0;
            __syncthreads();
            temp[threadIdx.x] += t;
            __syncthreads();
        }
        if (i < n) row_ptr[i + 1] = carry + temp[threadIdx.x];
        __syncthreads();
        if (threadIdx.x == 0) carry += temp[1023];
        __syncthreads();
    }
}

__global__ void cursor_kernel(const int* __restrict__ row_ptr, int* __restrict__ cur, int n) {
    int i = blockIdx.x * blockDim.x + threadIdx.x;
    if (i < n) cur[i] = row_ptr[i];
}

__global__ void scatter_kernel(const int* __restrict__ src, const int* __restrict__ dst,
                               int* __restrict__ cur, int* __restrict__ csr_src, int E) {
    int e = blockIdx.x * blockDim.x + threadIdx.x;
    if (e < E) {
        int p = atomicAdd(&cur[dst[e]], 1);
        csr_src[p] = src[e];
    }
}

// ---------------- GEMM: C[M,128] = A[M,K] @ W[K,128] + bias (opt gelu) ------
// A is A1 (stride 128) for cols < 128, A2 (stride 128) for cols >= 128 (concat).
// BM=128, BN=128, BK=8, 256 threads, 8x8 microtile.
__global__ __launch_bounds__(256) void gemm_kernel(
    const float* __restrict__ A1, const float* __restrict__ A2,
    const float* __restrict__ W, const float* __restrict__ bias,
    float* __restrict__ C, int M, int K, int act)
{
    __shared__ float As[8][128];
    __shared__ float Bs[8][128];

    int tid = threadIdx.x;
    int ty = tid >> 4;          // 0..15
    int tx = tid & 15;          // 0..15
    int rowBase = blockIdx.x * 128;

    int arow = tid >> 1;        // 0..127
    int ak   = (tid & 1) * 4;   // 0 or 4
    int brow = tid >> 5;        // 0..7
    int bcol = (tid & 31) * 4;  // 0..124

    float acc[8][8];
#pragma unroll
    for (int i = 0; i < 8; i++)
#pragma unroll
        for (int j = 0; j < 8; j++) acc[i][j] = 0.0f;

    for (int kt = 0; kt < K; kt += 8) {
        // load A tile
        float4 av = make_float4(0.f, 0.f, 0.f, 0.f);
        int grow = rowBase + arow;
        if (grow < M) {
            int kg = kt + ak;
            const float* Ap = A1;
            int kk = kg;
            if (A2 != nullptr && kg >= 128) { Ap = A2; kk = kg - 128; }
            av = *reinterpret_cast<const float4*>(Ap + (size_t)grow * 128 + kk);
        }
        As[ak + 0][arow] = av.x;
        As[ak + 1][arow] = av.y;
        As[ak + 2][arow] = av.z;
        As[ak + 3][arow] = av.w;
        // load B tile
        float4 bv = *reinterpret_cast<const float4*>(W + (size_t)(kt + brow) * 128 + bcol);
        *reinterpret_cast<float4*>(&Bs[brow][bcol]) = bv;
        __syncthreads();

#pragma unroll
        for (int k = 0; k < 8; k++) {
            float a[8], b[8];
            *reinterpret_cast<float4*>(a)     = *reinterpret_cast<const float4*>(&As[k][ty * 8]);
            *reinterpret_cast<float4*>(a + 4) = *reinterpret_cast<const float4*>(&As[k][ty * 8 + 4]);
            *reinterpret_cast<float4*>(b)     = *reinterpret_cast<const float4*>(&Bs[k][tx * 8]);
            *reinterpret_cast<float4*>(b + 4) = *reinterpret_cast<const float4*>(&Bs[k][tx * 8 + 4]);
#pragma unroll
            for (int i = 0; i < 8; i++)
#pragma unroll
                for (int j = 0; j < 8; j++) acc[i][j] = fmaf(a[i], b[j], acc[i][j]);
        }
        __syncthreads();
    }

    // epilogue
#pragma unroll
    for (int i = 0; i < 8; i++) {
        int r = rowBase + ty * 8 + i;
        if (r < M) {
            float out[8];
#pragma unroll
            for (int j = 0; j < 8; j++) {
                int col = tx * 8 + j;
                float v = acc[i][j] + bias[col];
                if (act) v = gelu_tanh(v);
                out[j] = v;
            }
            *reinterpret_cast<float4*>(C + (size_t)r * 128 + tx * 8)     = *reinterpret_cast<float4*>(out);
            *reinterpret_cast<float4*>(C + (size_t)r * 128 + tx * 8 + 4) = *reinterpret_cast<float4*>(out + 4);
        }
    }
}

// ---------------- GATv2 edge aggregation: one warp per dst node -------------
// fs,fd: [N,128]; attn: [4,32]; bout: [128]; online softmax per head.
__global__ __launch_bounds__(256) void gat_edge_kernel(
    const float* __restrict__ fs, const float* __restrict__ fd,
    const float* __restrict__ attn, const float* __restrict__ bout,
    const int* __restrict__ row_ptr, const int* __restrict__ csr_src,
    float* __restrict__ hout, int n_nodes)
{
    int warp = (blockIdx.x * blockDim.x + threadIdx.x) >> 5;
    int lane = threadIdx.x & 31;
    if (warp >= n_nodes) return;

    float fdv[4], attnv[4], m[4], s[4], acc[4];
#pragma unroll
    for (int k = 0; k < 4; k++) {
        fdv[k]   = fd[(size_t)warp * 128 + k * 32 + lane];
        attnv[k] = attn[k * 32 + lane];
        m[k] = -INFINITY; s[k] = 0.0f; acc[k] = 0.0f;
    }

    int beg = row_ptr[warp];
    int end = row_ptr[warp + 1];
    for (int e = beg; e < end; e++) {
        int sidx = csr_src[e];
        float fsv[4], part[4];
#pragma unroll
        for (int k = 0; k < 4; k++) {
            fsv[k] = fs[(size_t)sidx * 128 + k * 32 + lane];
            float ev = fsv[k] + fdv[k];
            ev = (ev > 0.0f) ? ev : 0.2f * ev;          // leaky relu, slope 0.2
            part[k] = ev * attnv[k];
        }
#pragma unroll
        for (int off = 16; off; off >>= 1) {
#pragma unroll
            for (int k = 0; k < 4; k++)
                part[k] += __shfl_xor_sync(0xffffffffu, part[k], off);
        }
#pragma unroll
        for (int k = 0; k < 4; k++) {
            float l  = part[k];
            float mn = fmaxf(m[k], l);
            float sc = __expf(m[k] - mn);
            float p  = __expf(l - mn);
            s[k]   = s[k] * sc + p;
            acc[k] = acc[k] * sc + p * fsv[k];
            m[k]   = mn;
        }
    }

#pragma unroll
    for (int k = 0; k < 4; k++) {
        float v = acc[k] / (s[k] + 1e-9f) + bout[k * 32 + lane];
        hout[(size_t)warp * 128 + k * 32 + lane] = gelu_tanh(v);
    }
}

// ---------------- launch ----------------
extern "C" void kernel_launch(void* const* d_in, const int* in_sizes, int n_in,
                              void* d_out, int out_size) {
    const float* x_t       = (const float*)d_in[0];
    const float* time_emb  = (const float*)d_in[1];
    const int*   src       = (const int*)d_in[2];
    const int*   dst       = (const int*)d_in[3];
    const float* W_init    = (const float*)d_in[4];
    const float* b_init    = (const float*)d_in[5];
    const float* Wsrc_down = (const float*)d_in[6];
    const float* bsrc_down = (const float*)d_in[7];
    const float* Wdst_down = (const float*)d_in[8];
    const float* bdst_down = (const float*)d_in[9];
    const float* attn_down = (const float*)d_in[10];
    const float* bout_down = (const float*)d_in[11];
    const float* Wsrc_mid  = (const float*)d_in[12];
    const float* bsrc_mid  = (const float*)d_in[13];
    const float* Wdst_mid  = (const float*)d_in[14];
    const float* bdst_mid  = (const float*)d_in[15];
    const float* attn_mid  = (const float*)d_in[16];
    const float* bout_mid  = (const float*)d_in[17];
    const float* Wsrc_up   = (const float*)d_in[18];
    const float* bsrc_up   = (const float*)d_in[19];
    const float* Wdst_up   = (const float*)d_in[20];
    const float* bdst_up   = (const float*)d_in[21];
    const float* attn_up   = (const float*)d_in[22];
    const float* bout_up   = (const float*)d_in[23];
    const float* W_fin     = (const float*)d_in[24];
    const float* b_fin     = (const float*)d_in[25];

    const int Nn = in_sizes[0] / HID;   // 50000
    const int E  = in_sizes[2];         // 800000

    void* pf; cudaGetSymbolAddress(&pf, g_buf);
    void* pi; cudaGetSymbolAddress(&pi, g_ibuf);
    float* base = (float*)pf;
    const size_t SL = (size_t)NN * HID;
    float* h0 = base + 0 * SL;
    float* h1 = base + 1 * SL;
    float* h2 = base + 2 * SL;
    float* h3 = base + 3 * SL;
    float* h4 = base + 4 * SL;
    float* h5 = base + 5 * SL;
    float* fs = base + 6 * SL;
    float* fd = base + 7 * SL;
    int* ib = (int*)pi;
    int* deg     = ib;
    int* row_ptr = deg + NN;
    int* cur     = row_ptr + NN + 1;
    int* csr     = cur + NN;

    dim3 tb(256);
    int gE = (E + 255) / 256;
    int gN = (Nn + 255) / 256;
    int gGemm = (Nn + 127) / 128;
    int gGat = (Nn * 32 + 255) / 256;

    // ---- CSR build ----
    cudaMemsetAsync(deg, 0, sizeof(int) * Nn);
    hist_kernel<<<gE, tb>>>(dst, deg, E);
    scan_kernel<<<1, 1024>>>(deg, row_ptr, Nn);
    cursor_kernel<<<gN, tb>>>(row_ptr, cur, Nn);
    scatter_kernel<<<gE, tb>>>(src, dst, cur, csr, E);

    // ---- init: h0 = gelu([x_t|time_emb] @ W_init + b_init), K=256 ----
    gemm_kernel<<<gGemm, tb>>>(x_t, time_emb, W_init, b_init, h0, Nn, 256, 1);

    const size_t WSZ = (size_t)HID * HID;      // 128*128
    const size_t WSZ2 = (size_t)2 * HID * HID; // 256*128

    // ---- down 0: h0 -> h1 ----
    gemm_kernel<<<gGemm, tb>>>(h0, nullptr, Wsrc_down + 0 * WSZ, bsrc_down + 0 * HID, fs, Nn, 128, 0);
    gemm_kernel<<<gGemm, tb>>>(h0, nullptr, Wdst_down + 0 * WSZ, bdst_down + 0 * HID, fd, Nn, 128, 0);
    gat_edge_kernel<<<gGat, tb>>>(fs, fd, attn_down + 0 * HID, bout_down + 0 * HID, row_ptr, csr, h1, Nn);

    // ---- down 1: h1 -> h2 ----
    gemm_kernel<<<gGemm, tb>>>(h1, nullptr, Wsrc_down + 1 * WSZ, bsrc_down + 1 * HID, fs, Nn, 128, 0);
    gemm_kernel<<<gGemm, tb>>>(h1, nullptr, Wdst_down + 1 * WSZ, bdst_down + 1 * HID, fd, Nn, 128, 0);
    gat_edge_kernel<<<gGat, tb>>>(fs, fd, attn_down + 1 * HID, bout_down + 1 * HID, row_ptr, csr, h2, Nn);

    // ---- mid: h2 -> h3 ----
    gemm_kernel<<<gGemm, tb>>>(h2, nullptr, Wsrc_mid, bsrc_mid, fs, Nn, 128, 0);
    gemm_kernel<<<gGemm, tb>>>(h2, nullptr, Wdst_mid, bdst_mid, fd, Nn, 128, 0);
    gat_edge_kernel<<<gGat, tb>>>(fs, fd, attn_mid, bout_mid, row_ptr, csr, h3, Nn);

    // ---- up 0: [h3|h1] -> h4 (skip = skips[1] = h1) ----
    gemm_kernel<<<gGemm, tb>>>(h3, h1, Wsrc_up + 0 * WSZ2, bsrc_up + 0 * HID, fs, Nn, 256, 0);
    gemm_kernel<<<gGemm, tb>>>(h3, h1, Wdst_up + 0 * WSZ2, bdst_up + 0 * HID, fd, Nn, 256, 0);
    gat_edge_kernel<<<gGat, tb>>>(fs, fd, attn_up + 0 * HID, bout_up + 0 * HID, row_ptr, csr, h4, Nn);

    // ---- up 1: [h4|h0] -> h5 (skip = skips[0] = h0) ----
    gemm_kernel<<<gGemm, tb>>>(h4, h0, Wsrc_up + 1 * WSZ2, bsrc_up + 1 * HID, fs, Nn, 256, 0);
    gemm_kernel<<<gGemm, tb>>>(h4, h0, Wdst_up + 1 * WSZ2, bdst_up + 1 * HID, fd, Nn, 256, 0);
    gat_edge_kernel<<<gGat, tb>>>(fs, fd, attn_up + 1 * HID, bout_up + 1 * HID, row_ptr, csr, h5, Nn);

    // ---- final: out = h5 @ W_fin + b_fin ; output tuple (out, h5) ----
    float* out = (float*)d_out;
    gemm_kernel<<<gGemm, tb>>>(h5, nullptr, W_fin, b_fin, out, Nn, 128, 0);
    if (out_size >= 2 * Nn * HID) {
        cudaMemcpyAsync(out + (size_t)Nn * HID, h5, (size_t)Nn * HID * sizeof(float),
                        cudaMemcpyDeviceToDevice);
    }
}

// round 2
// speedup vs baseline: 1.1859x; 1.1859x over previous
#include <cuda_runtime.h>
#include <cuda_bf16.h>
#include <math.h>

#define NN 50000
#define EE 800000
#define HID 128
#define NH 4
#define HD 32

typedef unsigned long long ull;

// ---------------- scratch (no allocation allowed) ----------------
__device__ float g_buf[(size_t)8 * NN * HID];
__device__ int g_ibuf[NN + (NN + 1) + NN + EE];

__device__ __forceinline__ float gelu_tanh(float x) {
    float x3 = x * x * x;
    float t = tanhf(0.7978845608028654f * (x + 0.044715f * x3));
    return 0.5f * x * (1.0f + t);
}

// packed f32x2 helpers (FFMA2 — ptxas never auto-fuses; HW supports it)
__device__ __forceinline__ void ffma2(ull& d, ull a, ull b) {
    asm("fma.rn.f32x2 %0, %1, %2, %0;" : "+l"(d) : "l"(a), "l"(b));
}
__device__ __forceinline__ ull dup2(float x) {
    ull r;
    asm("mov.b64 %0, {%1, %1};" : "=l"(r) : "f"(x));
    return r;
}
__device__ __forceinline__ float2 unpack2(ull v) {
    float2 r;
    asm("mov.b64 {%0, %1}, %2;" : "=f"(r.x), "=f"(r.y) : "l"(v));
    return r;
}

// ---------------- CSR build ----------------
__global__ void hist_kernel(const int* __restrict__ dst, int* __restrict__ deg, int E) {
    int e = blockIdx.x * blockDim.x + threadIdx.x;
    if (e < E) atomicAdd(&deg[dst[e]], 1);
}

__global__ void scan_kernel(const int* __restrict__ deg, int* __restrict__ row_ptr, int n) {
    __shared__ int temp[1024];
    __shared__ int carry;
    if (threadIdx.x == 0) { carry = 0; row_ptr[0] = 0; }
    __syncthreads();
    for (int base = 0; base < n; base += 1024) {
        int i = base + threadIdx.x;
        int v = (i < n) ? deg[i] : 0;
        temp[threadIdx.x] = v;
        __syncthreads();
        for (int off = 1; off < 1024; off <<= 1) {
            int t = (threadIdx.x >= off) ? temp[threadIdx.x - off] : 0;
            __syncthreads();
            temp[threadIdx.x] += t;
            __syncthreads();
        }
        if (i < n) row_ptr[i + 1] = carry + temp[threadIdx.x];
        __syncthreads();
        if (threadIdx.x == 0) carry += temp[1023];
        __syncthreads();
    }
}

__global__ void cursor_kernel(const int* __restrict__ row_ptr, int* __restrict__ cur, int n) {
    int i = blockIdx.x * blockDim.x + threadIdx.x;
    if (i < n) cur[i] = row_ptr[i];
}

__global__ void scatter_kernel(const int* __restrict__ src, const int* __restrict__ dst,
                               int* __restrict__ cur, int* __restrict__ csr_src, int E) {
    int e = blockIdx.x * blockDim.x + threadIdx.x;
    if (e < E) {
        int p = atomicAdd(&cur[dst[e]], 1);
        csr_src[p] = src[e];
    }
}

// ---------------- GEMM: C[M,128] = A[M,K] @ W[K,128] + bias ----------------
// A = [A1 | A2] concat along K (each stride 128). Dual-output: blockIdx.y
// selects (Wa,ba,Ca) or (Wb,bb,Cb). BM=128,BN=128,BK=16, 256 thr, 8x8 micro
// using packed fma.rn.f32x2. Register-prefetch double buffering.
__global__ __launch_bounds__(256) void gemm_kernel(
    const float* __restrict__ A1, const float* __restrict__ A2,
    const float* __restrict__ Wa, const float* __restrict__ ba, float* __restrict__ Ca,
    const float* __restrict__ Wb, const float* __restrict__ bb, float* __restrict__ Cb,
    int M, int K, int act)
{
    const float* W    = (blockIdx.y == 0) ? Wa : Wb;
    const float* bias = (blockIdx.y == 0) ? ba : bb;
    float*       C    = (blockIdx.y == 0) ? Ca : Cb;

    __shared__ float As[16 * 132];   // As[k][row], row stride 132 (16B aligned)
    __shared__ float Bs[16 * 128];   // Bs[k][col]

    const int tid = threadIdx.x;
    const int ty = tid >> 4;           // 0..15
    const int tx = tid & 15;           // 0..15
    const int rowBase = blockIdx.x * 128;

    // loader indices (2 float4 each for A and B)
    const int id0 = tid * 2, id1 = tid * 2 + 1;
    const int ar0 = id0 >> 2, aq0 = (id0 & 3) * 4;
    const int ar1 = id1 >> 2, aq1 = (id1 & 3) * 4;
    const int bk0 = id0 >> 5, bc0 = (id0 & 31) * 4;
    const int bk1 = id1 >> 5, bc1 = (id1 & 31) * 4;
    const int g0 = rowBase + ar0, g1 = rowBase + ar1;

    ull acc[8][4];
#pragma unroll
    for (int i = 0; i < 8; i++)
#pragma unroll
        for (int j = 0; j < 4; j++) acc[i][j] = 0ull;

    // ---- fetch helpers (inlined) ----
    float4 pa0, pa1, pb0, pb1;
    {   // tile 0 -> smem
        int kg0 = aq0, kg1 = aq1;
        float4 v0 = make_float4(0,0,0,0), v1 = make_float4(0,0,0,0);
        if (g0 < M) {
            const float* p = (A2 && kg0 >= 128) ? (A2 + (size_t)g0*128 + kg0-128) : (A1 + (size_t)g0*128 + kg0);
            v0 = *reinterpret_cast<const float4*>(p);
        }
        if (g1 < M) {
            const float* p = (A2 && kg1 >= 128) ? (A2 + (size_t)g1*128 + kg1-128) : (A1 + (size_t)g1*128 + kg1);
            v1 = *reinterpret_cast<const float4*>(p);
        }
        As[(aq0+0)*132 + ar0] = v0.x; As[(aq0+1)*132 + ar0] = v0.y;
        As[(aq0+2)*132 + ar0] = v0.z; As[(aq0+3)*132 + ar0] = v0.w;
        As[(aq1+0)*132 + ar1] = v1.x; As[(aq1+1)*132 + ar1] = v1.y;
        As[(aq1+2)*132 + ar1] = v1.z; As[(aq1+3)*132 + ar1] = v1.w;
        float4 w0 = *reinterpret_cast<const float4*>(W + (size_t)bk0*128 + bc0);
        float4 w1 = *reinterpret_cast<const float4*>(W + (size_t)bk1*128 + bc1);
        *reinterpret_cast<float4*>(&Bs[bk0*128 + bc0]) = w0;
        *reinterpret_cast<float4*>(&Bs[bk1*128 + bc1]) = w1;
    }
    __syncthreads();

    const int ktiles = K >> 4;
    for (int t = 0; t < ktiles; t++) {
        const bool more = (t + 1 < ktiles);
        if (more) {
            int kt = (t + 1) << 4;
            int kg0 = kt + aq0, kg1 = kt + aq1;
            pa0 = make_float4(0,0,0,0); pa1 = make_float4(0,0,0,0);
            if (g0 < M) {
                const float* p = (A2 && kg0 >= 128) ? (A2 + (size_t)g0*128 + kg0-128) : (A1 + (size_t)g0*128 + kg0);
                pa0 = *reinterpret_cast<const float4*>(p);
            }
            if (g1 < M) {
                const float* p = (A2 && kg1 >= 128) ? (A2 + (size_t)g1*128 + kg1-128) : (A1 + (size_t)g1*128 + kg1);
                pa1 = *reinterpret_cast<const float4*>(p);
            }
            pb0 = *reinterpret_cast<const float4*>(W + (size_t)(kt+bk0)*128 + bc0);
            pb1 = *reinterpret_cast<const float4*>(W + (size_t)(kt+bk1)*128 + bc1);
        }

#pragma unroll
        for (int k = 0; k < 16; k++) {
            const float* ar = &As[k*132 + ty*8];
            float4 av0 = *reinterpret_cast<const float4*>(ar);
            float4 av1 = *reinterpret_cast<const float4*>(ar + 4);
            ulonglong2 bq0 = *reinterpret_cast<const ulonglong2*>(&Bs[k*128 + tx*8]);
            ulonglong2 bq1 = *reinterpret_cast<const ulonglong2*>(&Bs[k*128 + tx*8 + 4]);
            ull b2[4] = {bq0.x, bq0.y, bq1.x, bq1.y};
            float a[8] = {av0.x, av0.y, av0.z, av0.w, av1.x, av1.y, av1.z, av1.w};
#pragma unroll
            for (int i = 0; i < 8; i++) {
                ull ad = dup2(a[i]);
#pragma unroll
                for (int j = 0; j < 4; j++) ffma2(acc[i][j], ad, b2[j]);
            }
        }

        if (more) {
            __syncthreads();
            As[(aq0+0)*132 + ar0] = pa0.x; As[(aq0+1)*132 + ar0] = pa0.y;
            As[(aq0+2)*132 + ar0] = pa0.z; As[(aq0+3)*132 + ar0] = pa0.w;
            As[(aq1+0)*132 + ar1] = pa1.x; As[(aq1+1)*132 + ar1] = pa1.y;
            As[(aq1+2)*132 + ar1] = pa1.z; As[(aq1+3)*132 + ar1] = pa1.w;
            *reinterpret_cast<float4*>(&Bs[bk0*128 + bc0]) = pb0;
            *reinterpret_cast<float4*>(&Bs[bk1*128 + bc1]) = pb1;
            __syncthreads();
        }
    }

    // epilogue
    float bl[8];
#pragma unroll
    for (int j = 0; j < 8; j++) bl[j] = bias[tx*8 + j];
#pragma unroll
    for (int i = 0; i < 8; i++) {
        int r = rowBase + ty*8 + i;
        if (r < M) {
            float out[8];
#pragma unroll
            for (int j = 0; j < 4; j++) {
                float2 v = unpack2(acc[i][j]);
                out[j*2]   = v.x + bl[j*2];
                out[j*2+1] = v.y + bl[j*2+1];
            }
            if (act) {
#pragma unroll
                for (int j = 0; j < 8; j++) out[j] = gelu_tanh(out[j]);
            }
            *reinterpret_cast<float4*>(C + (size_t)r*128 + tx*8)     = *reinterpret_cast<float4*>(out);
            *reinterpret_cast<float4*>(C + (size_t)r*128 + tx*8 + 4) = *reinterpret_cast<float4*>(out + 4);
        }
    }
}

// ---------------- GATv2 edge aggregation: one warp per dst node -------------
__global__ __launch_bounds__(256) void gat_edge_kernel(
    const float* __restrict__ fs, const float* __restrict__ fd,
    const float* __restrict__ attn, const float* __restrict__ bout,
    const int* __restrict__ row_ptr, const int* __restrict__ csr_src,
    float* __restrict__ hout, int n_nodes)
{
    int warp = (blockIdx.x * blockDim.x + threadIdx.x) >> 5;
    int lane = threadIdx.x & 31;
    if (warp >= n_nodes) return;

    float fdv[4], attnv[4], m[4], s[4], acc[4];
#pragma unroll
    for (int k = 0; k < 4; k++) {
        fdv[k]   = fd[(size_t)warp * 128 + k * 32 + lane];
        attnv[k] = attn[k * 32 + lane];
        m[k] = -INFINITY; s[k] = 0.0f; acc[k] = 0.0f;
    }

    int beg = row_ptr[warp];
    int end = row_ptr[warp + 1];
    for (int e = beg; e < end; e++) {
        int sidx = csr_src[e];
        float fsv[4], part[4];
#pragma unroll
        for (int k = 0; k < 4; k++) {
            fsv[k] = fs[(size_t)sidx * 128 + k * 32 + lane];
            float ev = fsv[k] + fdv[k];
            ev = (ev > 0.0f) ? ev : 0.2f * ev;
            part[k] = ev * attnv[k];
        }
#pragma unroll
        for (int off = 16; off; off >>= 1) {
#pragma unroll
            for (int k = 0; k < 4; k++)
                part[k] += __shfl_xor_sync(0xffffffffu, part[k], off);
        }
#pragma unroll
        for (int k = 0; k < 4; k++) {
            float l  = part[k];
            float mn = fmaxf(m[k], l);
            float sc = __expf(m[k] - mn);
            float p  = __expf(l - mn);
            s[k]   = s[k] * sc + p;
            acc[k] = acc[k] * sc + p * fsv[k];
            m[k]   = mn;
        }
    }

#pragma unroll
    for (int k = 0; k < 4; k++) {
        float v = acc[k] / (s[k] + 1e-9f) + bout[k * 32 + lane];
        hout[(size_t)warp * 128 + k * 32 + lane] = gelu_tanh(v);
    }
}

// ---------------- launch ----------------
extern "C" void kernel_launch(void* const* d_in, const int* in_sizes, int n_in,
                              void* d_out, int out_size) {
    const float* x_t       = (const float*)d_in[0];
    const float* time_emb  = (const float*)d_in[1];
    const int*   src       = (const int*)d_in[2];
    const int*   dst       = (const int*)d_in[3];
    const float* W_init    = (const float*)d_in[4];
    const float* b_init    = (const float*)d_in[5];
    const float* Wsrc_down = (const float*)d_in[6];
    const float* bsrc_down = (const float*)d_in[7];
    const float* Wdst_down = (const float*)d_in[8];
    const float* bdst_down = (const float*)d_in[9];
    const float* attn_down = (const float*)d_in[10];
    const float* bout_down = (const float*)d_in[11];
    const float* Wsrc_mid  = (const float*)d_in[12];
    const float* bsrc_mid  = (const float*)d_in[13];
    const float* Wdst_mid  = (const float*)d_in[14];
    const float* bdst_mid  = (const float*)d_in[15];
    const float* attn_mid  = (const float*)d_in[16];
    const float* bout_mid  = (const float*)d_in[17];
    const float* Wsrc_up   = (const float*)d_in[18];
    const float* bsrc_up   = (const float*)d_in[19];
    const float* Wdst_up   = (const float*)d_in[20];
    const float* bdst_up   = (const float*)d_in[21];
    const float* attn_up   = (const float*)d_in[22];
    const float* bout_up   = (const float*)d_in[23];
    const float* W_fin     = (const float*)d_in[24];
    const float* b_fin     = (const float*)d_in[25];

    const int Nn = in_sizes[0] / HID;   // 50000
    const int E  = in_sizes[2];         // 800000

    void* pf; cudaGetSymbolAddress(&pf, g_buf);
    void* pi; cudaGetSymbolAddress(&pi, g_ibuf);
    float* base = (float*)pf;
    const size_t SL = (size_t)NN * HID;
    float* h0 = base + 0 * SL;
    float* h1 = base + 1 * SL;
    float* h2 = base + 2 * SL;
    float* h3 = base + 3 * SL;
    float* h4 = base + 4 * SL;
    float* h5 = base + 5 * SL;
    float* fs = base + 6 * SL;
    float* fd = base + 7 * SL;
    int* ib = (int*)pi;
    int* deg     = ib;
    int* row_ptr = deg + NN;
    int* cur     = row_ptr + NN + 1;
    int* csr     = cur + NN;

    float* out = (float*)d_out;
    // last GAT layer writes h directly into output region when it fits
    float* hfin = (out_size >= 2 * Nn * HID) ? (out + (size_t)Nn * HID) : h5;

    dim3 tb(256);
    int gE = (E + 255) / 256;
    int gN = (Nn + 255) / 256;
    int gx = (Nn + 127) / 128;
    dim3 g1(gx, 1), g2(gx, 2);
    int gGat = (Nn * 32 + 255) / 256;

    // ---- CSR build ----
    cudaMemsetAsync(deg, 0, sizeof(int) * Nn);
    hist_kernel<<<gE, tb>>>(dst, deg, E);
    scan_kernel<<<1, 1024>>>(deg, row_ptr, Nn);
    cursor_kernel<<<gN, tb>>>(row_ptr, cur, Nn);
    scatter_kernel<<<gE, tb>>>(src, dst, cur, csr, E);

    // ---- init: h0 = gelu([x_t|time_emb] @ W_init + b_init), K=256 ----
    gemm_kernel<<<g1, tb>>>(x_t, time_emb, W_init, b_init, h0,
                            nullptr, nullptr, nullptr, Nn, 256, 1);

    const size_t WSZ  = (size_t)HID * HID;
    const size_t WSZ2 = (size_t)2 * HID * HID;

    // ---- down 0 ----
    gemm_kernel<<<g2, tb>>>(h0, nullptr, Wsrc_down, bsrc_down, fs,
                            Wdst_down, bdst_down, fd, Nn, 128, 0);
    gat_edge_kernel<<<gGat, tb>>>(fs, fd, attn_down, bout_down, row_ptr, csr, h1, Nn);

    // ---- down 1 ----
    gemm_kernel<<<g2, tb>>>(h1, nullptr, Wsrc_down + WSZ, bsrc_down + HID, fs,
                            Wdst_down + WSZ, bdst_down + HID, fd, Nn, 128, 0);
    gat_edge_kernel<<<gGat, tb>>>(fs, fd, attn_down + HID, bout_down + HID, row_ptr, csr, h2, Nn);

    // ---- mid ----
    gemm_kernel<<<g2, tb>>>(h2, nullptr, Wsrc_mid, bsrc_mid, fs,
                            Wdst_mid, bdst_mid, fd, Nn, 128, 0);
    gat_edge_kernel<<<gGat, tb>>>(fs, fd, attn_mid, bout_mid, row_ptr, csr, h3, Nn);

    // ---- up 0: [h3|h1] ----
    gemm_kernel<<<g2, tb>>>(h3, h1, Wsrc_up, bsrc_up, fs,
                            Wdst_up, bdst_up, fd, Nn, 256, 0);
    gat_edge_kernel<<<gGat, tb>>>(fs, fd, attn_up, bout_up, row_ptr, csr, h4, Nn);

    // ---- up 1: [h4|h0] ----
    gemm_kernel<<<g2, tb>>>(h4, h0, Wsrc_up + WSZ2, bsrc_up + HID, fs,
                            Wdst_up + WSZ2, bdst_up + HID, fd, Nn, 256, 0);
    gat_edge_kernel<<<gGat, tb>>>(fs, fd, attn_up + HID, bout_up + HID, row_ptr, csr, hfin, Nn);

    // ---- final: out = hfin @ W_fin + b_fin ----
    gemm_kernel<<<g1, tb>>>(hfin, nullptr, W_fin, b_fin, out,
                            nullptr, nullptr, nullptr, Nn, 128, 0);
    if (hfin == h5) {
        cudaMemcpyAsync(out + (size_t)Nn * HID, h5, (size_t)Nn * HID * sizeof(float),
                        cudaMemcpyDeviceToDevice);
    }
}

// round 3
// speedup vs baseline: 1.6450x; 1.3872x over previous
#include <cuda_runtime.h>
#include <cuda_bf16.h>
#include <math.h>

#define NN 50000
#define EE 800000
#define HID 128
#define NH 4
#define HD 32

typedef unsigned long long ull;

// ---------------- scratch (no allocation allowed) ----------------
__device__ float g_buf[(size_t)8 * NN * HID];
__device__ int g_ibuf[NN + (NN + 1) + NN + EE];

__device__ __forceinline__ float gelu_tanh(float x) {
    float x3 = x * x * x;
    float t = tanhf(0.7978845608028654f * (x + 0.044715f * x3));
    return 0.5f * x * (1.0f + t);
}

// packed f32x2 helpers
__device__ __forceinline__ void ffma2(ull& d, ull a, ull b) {
    asm("fma.rn.f32x2 %0, %1, %2, %0;" : "+l"(d) : "l"(a), "l"(b));
}
__device__ __forceinline__ ull dup2(float x) {
    ull r;
    asm("mov.b64 %0, {%1, %1};" : "=l"(r) : "f"(x));
    return r;
}
__device__ __forceinline__ float2 unpack2(ull v) {
    float2 r;
    asm("mov.b64 {%0, %1}, %2;" : "=f"(r.x), "=f"(r.y) : "l"(v));
    return r;
}

// ---------------- CSR build ----------------
__global__ void hist_kernel(const int* __restrict__ dst, int* __restrict__ deg, int E) {
    int e = blockIdx.x * blockDim.x + threadIdx.x;
    if (e < E) atomicAdd(&deg[dst[e]], 1);
}

// shfl-based inclusive scan, 1024 threads, serial over chunks
__global__ void scan_kernel(const int* __restrict__ deg, int* __restrict__ row_ptr, int n) {
    __shared__ int wsum[32];
    __shared__ int carry;
    const int lane = threadIdx.x & 31, wid = threadIdx.x >> 5;
    if (threadIdx.x == 0) { carry = 0; row_ptr[0] = 0; }
    __syncthreads();
    for (int base = 0; base < n; base += 1024) {
        int i = base + threadIdx.x;
        int x = (i < n) ? deg[i] : 0;
#pragma unroll
        for (int o = 1; o < 32; o <<= 1) {
            int t = __shfl_up_sync(0xffffffffu, x, o);
            if (lane >= o) x += t;
        }
        if (lane == 31) wsum[wid] = x;
        __syncthreads();
        if (wid == 0) {
            int y = wsum[lane];
#pragma unroll
            for (int o = 1; o < 32; o <<= 1) {
                int t = __shfl_up_sync(0xffffffffu, y, o);
                if (lane >= o) y += t;
            }
            wsum[lane] = y;
        }
        __syncthreads();
        int off = carry + (wid > 0 ? wsum[wid - 1] : 0);
        if (i < n) row_ptr[i + 1] = off + x;
        __syncthreads();
        if (threadIdx.x == 0) carry += wsum[31];
        __syncthreads();
    }
}

__global__ void cursor_kernel(const int* __restrict__ row_ptr, int* __restrict__ cur, int n) {
    int i = blockIdx.x * blockDim.x + threadIdx.x;
    if (i < n) cur[i] = row_ptr[i];
}

__global__ void scatter_kernel(const int* __restrict__ src, const int* __restrict__ dst,
                               int* __restrict__ cur, int* __restrict__ csr_src, int E) {
    int e = blockIdx.x * blockDim.x + threadIdx.x;
    if (e < E) {
        int p = atomicAdd(&cur[dst[e]], 1);
        csr_src[p] = src[e];
    }
}

// ---------------- GEMM: C[M,128] = A[M,K] @ W[K,128] + bias ----------------
__global__ __launch_bounds__(256) void gemm_kernel(
    const float* __restrict__ A1, const float* __restrict__ A2,
    const float* __restrict__ Wa, const float* __restrict__ ba, float* __restrict__ Ca,
    const float* __restrict__ Wb, const float* __restrict__ bb, float* __restrict__ Cb,
    int M, int K, int act)
{
    const float* W    = (blockIdx.y == 0) ? Wa : Wb;
    const float* bias = (blockIdx.y == 0) ? ba : bb;
    float*       C    = (blockIdx.y == 0) ? Ca : Cb;

    __shared__ float As[16 * 132];
    __shared__ float Bs[16 * 128];

    const int tid = threadIdx.x;
    const int ty = tid >> 4;
    const int tx = tid & 15;
    const int rowBase = blockIdx.x * 128;

    const int id0 = tid * 2, id1 = tid * 2 + 1;
    const int ar0 = id0 >> 2, aq0 = (id0 & 3) * 4;
    const int ar1 = id1 >> 2, aq1 = (id1 & 3) * 4;
    const int bk0 = id0 >> 5, bc0 = (id0 & 31) * 4;
    const int bk1 = id1 >> 5, bc1 = (id1 & 31) * 4;
    const int g0 = rowBase + ar0, g1 = rowBase + ar1;

    ull acc[8][4];
#pragma unroll
    for (int i = 0; i < 8; i++)
#pragma unroll
        for (int j = 0; j < 4; j++) acc[i][j] = 0ull;

    float4 pa0, pa1, pb0, pb1;
    {
        int kg0 = aq0, kg1 = aq1;
        float4 v0 = make_float4(0,0,0,0), v1 = make_float4(0,0,0,0);
        if (g0 < M) {
            const float* p = (A2 && kg0 >= 128) ? (A2 + (size_t)g0*128 + kg0-128) : (A1 + (size_t)g0*128 + kg0);
            v0 = *reinterpret_cast<const float4*>(p);
        }
        if (g1 < M) {
            const float* p = (A2 && kg1 >= 128) ? (A2 + (size_t)g1*128 + kg1-128) : (A1 + (size_t)g1*128 + kg1);
            v1 = *reinterpret_cast<const float4*>(p);
        }
        As[(aq0+0)*132 + ar0] = v0.x; As[(aq0+1)*132 + ar0] = v0.y;
        As[(aq0+2)*132 + ar0] = v0.z; As[(aq0+3)*132 + ar0] = v0.w;
        As[(aq1+0)*132 + ar1] = v1.x; As[(aq1+1)*132 + ar1] = v1.y;
        As[(aq1+2)*132 + ar1] = v1.z; As[(aq1+3)*132 + ar1] = v1.w;
        float4 w0 = *reinterpret_cast<const float4*>(W + (size_t)bk0*128 + bc0);
        float4 w1 = *reinterpret_cast<const float4*>(W + (size_t)bk1*128 + bc1);
        *reinterpret_cast<float4*>(&Bs[bk0*128 + bc0]) = w0;
        *reinterpret_cast<float4*>(&Bs[bk1*128 + bc1]) = w1;
    }
    __syncthreads();

    const int ktiles = K >> 4;
    for (int t = 0; t < ktiles; t++) {
        const bool more = (t + 1 < ktiles);
        if (more) {
            int kt = (t + 1) << 4;
            int kg0 = kt + aq0, kg1 = kt + aq1;
            pa0 = make_float4(0,0,0,0); pa1 = make_float4(0,0,0,0);
            if (g0 < M) {
                const float* p = (A2 && kg0 >= 128) ? (A2 + (size_t)g0*128 + kg0-128) : (A1 + (size_t)g0*128 + kg0);
                pa0 = *reinterpret_cast<const float4*>(p);
            }
            if (g1 < M) {
                const float* p = (A2 && kg1 >= 128) ? (A2 + (size_t)g1*128 + kg1-128) : (A1 + (size_t)g1*128 + kg1);
                pa1 = *reinterpret_cast<const float4*>(p);
            }
            pb0 = *reinterpret_cast<const float4*>(W + (size_t)(kt+bk0)*128 + bc0);
            pb1 = *reinterpret_cast<const float4*>(W + (size_t)(kt+bk1)*128 + bc1);
        }

#pragma unroll
        for (int k = 0; k < 16; k++) {
            const float* ar = &As[k*132 + ty*8];
            float4 av0 = *reinterpret_cast<const float4*>(ar);
            float4 av1 = *reinterpret_cast<const float4*>(ar + 4);
            ulonglong2 bq0 = *reinterpret_cast<const ulonglong2*>(&Bs[k*128 + tx*8]);
            ulonglong2 bq1 = *reinterpret_cast<const ulonglong2*>(&Bs[k*128 + tx*8 + 4]);
            ull b2[4] = {bq0.x, bq0.y, bq1.x, bq1.y};
            float a[8] = {av0.x, av0.y, av0.z, av0.w, av1.x, av1.y, av1.z, av1.w};
#pragma unroll
            for (int i = 0; i < 8; i++) {
                ull ad = dup2(a[i]);
#pragma unroll
                for (int j = 0; j < 4; j++) ffma2(acc[i][j], ad, b2[j]);
            }
        }

        if (more) {
            __syncthreads();
            As[(aq0+0)*132 + ar0] = pa0.x; As[(aq0+1)*132 + ar0] = pa0.y;
            As[(aq0+2)*132 + ar0] = pa0.z; As[(aq0+3)*132 + ar0] = pa0.w;
            As[(aq1+0)*132 + ar1] = pa1.x; As[(aq1+1)*132 + ar1] = pa1.y;
            As[(aq1+2)*132 + ar1] = pa1.z; As[(aq1+3)*132 + ar1] = pa1.w;
            *reinterpret_cast<float4*>(&Bs[bk0*128 + bc0]) = pb0;
            *reinterpret_cast<float4*>(&Bs[bk1*128 + bc1]) = pb1;
            __syncthreads();
        }
    }

    float bl[8];
#pragma unroll
    for (int j = 0; j < 8; j++) bl[j] = bias[tx*8 + j];
#pragma unroll
    for (int i = 0; i < 8; i++) {
        int r = rowBase + ty*8 + i;
        if (r < M) {
            float out[8];
#pragma unroll
            for (int j = 0; j < 4; j++) {
                float2 v = unpack2(acc[i][j]);
                out[j*2]   = v.x + bl[j*2];
                out[j*2+1] = v.y + bl[j*2+1];
            }
            if (act) {
#pragma unroll
                for (int j = 0; j < 8; j++) out[j] = gelu_tanh(out[j]);
            }
            *reinterpret_cast<float4*>(C + (size_t)r*128 + tx*8)     = *reinterpret_cast<float4*>(out);
            *reinterpret_cast<float4*>(C + (size_t)r*128 + tx*8 + 4) = *reinterpret_cast<float4*>(out + 4);
        }
    }
}

// ---------------- GATv2 edge aggregation ----------------
// One warp per dst node. Lane l handles head h = l>>3, elems (l&7)*4..+3.
// Dot over each head's 32 elems = 3-shfl butterfly within 8-lane group.
__device__ __forceinline__ float edge_logit(float4 f, float4 fdv, float4 attnv, float4& evout) {
    float4 ev;
    ev.x = f.x + fdv.x; ev.x = (ev.x > 0.f) ? ev.x : 0.2f * ev.x;
    ev.y = f.y + fdv.y; ev.y = (ev.y > 0.f) ? ev.y : 0.2f * ev.y;
    ev.z = f.z + fdv.z; ev.z = (ev.z > 0.f) ? ev.z : 0.2f * ev.z;
    ev.w = f.w + fdv.w; ev.w = (ev.w > 0.f) ? ev.w : 0.2f * ev.w;
    evout = ev;
    return ev.x * attnv.x + ev.y * attnv.y + ev.z * attnv.z + ev.w * attnv.w;
}

__global__ __launch_bounds__(256) void gat_edge_kernel(
    const float* __restrict__ fs, const float* __restrict__ fd,
    const float* __restrict__ attn, const float* __restrict__ bout,
    const int* __restrict__ row_ptr, const int* __restrict__ csr_src,
    float* __restrict__ hout, int n_nodes)
{
    const int warp = (blockIdx.x * blockDim.x + threadIdx.x) >> 5;
    const int lane = threadIdx.x & 31;
    if (warp >= n_nodes) return;

    const int off = lane * 4;            // == (l>>3)*32 + (l&7)*4
    const int nodeBase = warp * 128;

    const float4 fdv   = *reinterpret_cast<const float4*>(fd + nodeBase + off);
    const float4 attnv = *reinterpret_cast<const float4*>(attn + off);

    float m = -INFINITY, s = 0.0f;
    float4 acc = make_float4(0.f, 0.f, 0.f, 0.f);

    int e = row_ptr[warp];
    const int end = row_ptr[warp + 1];

    for (; e + 2 <= end; e += 2) {
        int s0 = csr_src[e], s1 = csr_src[e + 1];
        float4 f0 = *reinterpret_cast<const float4*>(fs + s0 * 128 + off);
        float4 f1 = *reinterpret_cast<const float4*>(fs + s1 * 128 + off);
        float4 ev0, ev1;
        float l0 = edge_logit(f0, fdv, attnv, ev0);
        float l1 = edge_logit(f1, fdv, attnv, ev1);
        l0 += __shfl_xor_sync(0xffffffffu, l0, 1);
        l1 += __shfl_xor_sync(0xffffffffu, l1, 1);
        l0 += __shfl_xor_sync(0xffffffffu, l0, 2);
        l1 += __shfl_xor_sync(0xffffffffu, l1, 2);
        l0 += __shfl_xor_sync(0xffffffffu, l0, 4);
        l1 += __shfl_xor_sync(0xffffffffu, l1, 4);
        {
            float mn = fmaxf(m, l0);
            float sc = __expf(m - mn);
            float p  = __expf(l0 - mn);
            s = s * sc + p;
            acc.x = acc.x * sc + p * f0.x;
            acc.y = acc.y * sc + p * f0.y;
            acc.z = acc.z * sc + p * f0.z;
            acc.w = acc.w * sc + p * f0.w;
            m = mn;
        }
        {
            float mn = fmaxf(m, l1);
            float sc = __expf(m - mn);
            float p  = __expf(l1 - mn);
            s = s * sc + p;
            acc.x = acc.x * sc + p * f1.x;
            acc.y = acc.y * sc + p * f1.y;
            acc.z = acc.z * sc + p * f1.z;
            acc.w = acc.w * sc + p * f1.w;
            m = mn;
        }
    }
    if (e < end) {
        int s0 = csr_src[e];
        float4 f0 = *reinterpret_cast<const float4*>(fs + s0 * 128 + off);
        float4 ev0;
        float l0 = edge_logit(f0, fdv, attnv, ev0);
        l0 += __shfl_xor_sync(0xffffffffu, l0, 1);
        l0 += __shfl_xor_sync(0xffffffffu, l0, 2);
        l0 += __shfl_xor_sync(0xffffffffu, l0, 4);
        float mn = fmaxf(m, l0);
        float sc = __expf(m - mn);
        float p  = __expf(l0 - mn);
        s = s * sc + p;
        acc.x = acc.x * sc + p * f0.x;
        acc.y = acc.y * sc + p * f0.y;
        acc.z = acc.z * sc + p * f0.z;
        acc.w = acc.w * sc + p * f0.w;
        m = mn;
    }

    const float4 bv = *reinterpret_cast<const float4*>(bout + off);
    float inv = 1.0f / (s + 1e-9f);
    float4 o;
    o.x = gelu_tanh(acc.x * inv + bv.x);
    o.y = gelu_tanh(acc.y * inv + bv.y);
    o.z = gelu_tanh(acc.z * inv + bv.z);
    o.w = gelu_tanh(acc.w * inv + bv.w);
    *reinterpret_cast<float4*>(hout + nodeBase + off) = o;
}

// ---------------- launch ----------------
extern "C" void kernel_launch(void* const* d_in, const int* in_sizes, int n_in,
                              void* d_out, int out_size) {
    const float* x_t       = (const float*)d_in[0];
    const float* time_emb  = (const float*)d_in[1];
    const int*   src       = (const int*)d_in[2];
    const int*   dst       = (const int*)d_in[3];
    const float* W_init    = (const float*)d_in[4];
    const float* b_init    = (const float*)d_in[5];
    const float* Wsrc_down = (const float*)d_in[6];
    const float* bsrc_down = (const float*)d_in[7];
    const float* Wdst_down = (const float*)d_in[8];
    const float* bdst_down = (const float*)d_in[9];
    const float* attn_down = (const float*)d_in[10];
    const float* bout_down = (const float*)d_in[11];
    const float* Wsrc_mid  = (const float*)d_in[12];
    const float* bsrc_mid  = (const float*)d_in[13];
    const float* Wdst_mid  = (const float*)d_in[14];
    const float* bdst_mid  = (const float*)d_in[15];
    const float* attn_mid  = (const float*)d_in[16];
    const float* bout_mid  = (const float*)d_in[17];
    const float* Wsrc_up   = (const float*)d_in[18];
    const float* bsrc_up   = (const float*)d_in[19];
    const float* Wdst_up   = (const float*)d_in[20];
    const float* bdst_up   = (const float*)d_in[21];
    const float* attn_up   = (const float*)d_in[22];
    const float* bout_up   = (const float*)d_in[23];
    const float* W_fin     = (const float*)d_in[24];
    const float* b_fin     = (const float*)d_in[25];

    const int Nn = in_sizes[0] / HID;
    const int E  = in_sizes[2];

    void* pf; cudaGetSymbolAddress(&pf, g_buf);
    void* pi; cudaGetSymbolAddress(&pi, g_ibuf);
    float* base = (float*)pf;
    const size_t SL = (size_t)NN * HID;
    float* h0 = base + 0 * SL;
    float* h1 = base + 1 * SL;
    float* h2 = base + 2 * SL;
    float* h3 = base + 3 * SL;
    float* h4 = base + 4 * SL;
    float* h5 = base + 5 * SL;
    float* fs = base + 6 * SL;
    float* fd = base + 7 * SL;
    int* ib = (int*)pi;
    int* deg     = ib;
    int* row_ptr = deg + NN;
    int* cur     = row_ptr + NN + 1;
    int* csr     = cur + NN;

    float* out = (float*)d_out;
    float* hfin = (out_size >= 2 * Nn * HID) ? (out + (size_t)Nn * HID) : h5;

    dim3 tb(256);
    int gE = (E + 255) / 256;
    int gN = (Nn + 255) / 256;
    int gx = (Nn + 127) / 128;
    dim3 g1(gx, 1), g2(gx, 2);
    int gGat = (Nn * 32 + 255) / 256;

    cudaMemsetAsync(deg, 0, sizeof(int) * Nn);
    hist_kernel<<<gE, tb>>>(dst, deg, E);
    scan_kernel<<<1, 1024>>>(deg, row_ptr, Nn);
    cursor_kernel<<<gN, tb>>>(row_ptr, cur, Nn);
    scatter_kernel<<<gE, tb>>>(src, dst, cur, csr, E);

    gemm_kernel<<<g1, tb>>>(x_t, time_emb, W_init, b_init, h0,
                            nullptr, nullptr, nullptr, Nn, 256, 1);

    const size_t WSZ  = (size_t)HID * HID;
    const size_t WSZ2 = (size_t)2 * HID * HID;

    gemm_kernel<<<g2, tb>>>(h0, nullptr, Wsrc_down, bsrc_down, fs,
                            Wdst_down, bdst_down, fd, Nn, 128, 0);
    gat_edge_kernel<<<gGat, tb>>>(fs, fd, attn_down, bout_down, row_ptr, csr, h1, Nn);

    gemm_kernel<<<g2, tb>>>(h1, nullptr, Wsrc_down + WSZ, bsrc_down + HID, fs,
                            Wdst_down + WSZ, bdst_down + HID, fd, Nn, 128, 0);
    gat_edge_kernel<<<gGat, tb>>>(fs, fd, attn_down + HID, bout_down + HID, row_ptr, csr, h2, Nn);

    gemm_kernel<<<g2, tb>>>(h2, nullptr, Wsrc_mid, bsrc_mid, fs,
                            Wdst_mid, bdst_mid, fd, Nn, 128, 0);
    gat_edge_kernel<<<gGat, tb>>>(fs, fd, attn_mid, bout_mid, row_ptr, csr, h3, Nn);

    gemm_kernel<<<g2, tb>>>(h3, h1, Wsrc_up, bsrc_up, fs,
                            Wdst_up, bdst_up, fd, Nn, 256, 0);
    gat_edge_kernel<<<gGat, tb>>>(fs, fd, attn_up, bout_up, row_ptr, csr, h4, Nn);

    gemm_kernel<<<g2, tb>>>(h4, h0, Wsrc_up + WSZ2, bsrc_up + HID, fs,
                            Wdst_up + WSZ2, bdst_up + HID, fd, Nn, 256, 0);
    gat_edge_kernel<<<gGat, tb>>>(fs, fd, attn_up + HID, bout_up + HID, row_ptr, csr, hfin, Nn);

    gemm_kernel<<<g1, tb>>>(hfin, nullptr, W_fin, b_fin, out,
                            nullptr, nullptr, nullptr, Nn, 128, 0);
    if (hfin == h5) {
        cudaMemcpyAsync(out + (size_t)Nn * HID, h5, (size_t)Nn * HID * sizeof(float),
                        cudaMemcpyDeviceToDevice);
    }
}